// round 4
// baseline (speedup 1.0000x reference)
#include <cuda_runtime.h>
#include <cstdint>

#define D 64
#define NODE_STRIDE 256        // 4 layers * 64 floats, node-major [n][4][64]
#define MAX_NODES   150016
#define MAX_EDGES   3000000
#define SCAN_BS     512

// ---------------------------------------------------------------------------
// Static scratch (allocation-free rule: __device__ globals)
// ---------------------------------------------------------------------------
__device__ int  d_cnt[MAX_NODES];
__device__ int  d_row_ptr[MAX_NODES + 1];
__device__ int  d_cursor[MAX_NODES];
__device__ int  d_bsums[SCAN_BS];
__device__ int2 d_edges_sorted[MAX_EDGES];   // (col, val bits), grouped by row

// ---------------------------------------------------------------------------
// CSR build
// ---------------------------------------------------------------------------
__global__ void lgcn_hist4(const int* __restrict__ edge_row, int n_edges) {
    int t = blockIdx.x * blockDim.x + threadIdx.x;
    int e = t * 4;
    if (e + 3 < n_edges) {
        int4 r = *reinterpret_cast<const int4*>(edge_row + e);
        atomicAdd(&d_cnt[r.x], 1);
        atomicAdd(&d_cnt[r.y], 1);
        atomicAdd(&d_cnt[r.z], 1);
        atomicAdd(&d_cnt[r.w], 1);
    } else {
        for (; e < n_edges; ++e) atomicAdd(&d_cnt[edge_row[e]], 1);
    }
}

__global__ void lgcn_scan_blocks(int n) {
    __shared__ int s[SCAN_BS];
    int t = threadIdx.x;
    int i = blockIdx.x * SCAN_BS + t;
    int v = (i < n) ? d_cnt[i] : 0;
    s[t] = v;
    __syncthreads();
    #pragma unroll
    for (int off = 1; off < SCAN_BS; off <<= 1) {
        int tmp = (t >= off) ? s[t - off] : 0;
        __syncthreads();
        s[t] += tmp;
        __syncthreads();
    }
    if (i < n) d_row_ptr[i] = s[t] - v;      // exclusive
    if (t == SCAN_BS - 1) d_bsums[blockIdx.x] = s[t];
}

__global__ void lgcn_scan_sums(int nb) {
    __shared__ int s[SCAN_BS];
    int t = threadIdx.x;
    int v = (t < nb) ? d_bsums[t] : 0;
    s[t] = v;
    __syncthreads();
    #pragma unroll
    for (int off = 1; off < SCAN_BS; off <<= 1) {
        int tmp = (t >= off) ? s[t - off] : 0;
        __syncthreads();
        s[t] += tmp;
        __syncthreads();
    }
    if (t < nb) d_bsums[t] = s[t] - v;       // exclusive
}

__global__ void lgcn_scan_add(int n, int n_edges) {
    int i = blockIdx.x * blockDim.x + threadIdx.x;
    if (i < n) {
        int p = d_row_ptr[i] + d_bsums[i / SCAN_BS];
        d_row_ptr[i] = p;
        d_cursor[i]  = p;
    }
    if (i == 0) d_row_ptr[n] = n_edges;
}

__global__ void lgcn_scatter4(const int*   __restrict__ edge_row,
                              const int*   __restrict__ edge_col,
                              const float* __restrict__ edge_val,
                              int n_edges) {
    int t = blockIdx.x * blockDim.x + threadIdx.x;
    int e = t * 4;
    if (e + 3 < n_edges) {
        int4   r = *reinterpret_cast<const int4*>(edge_row + e);
        int4   c = *reinterpret_cast<const int4*>(edge_col + e);
        float4 v = *reinterpret_cast<const float4*>(edge_val + e);
        int p0 = atomicAdd(&d_cursor[r.x], 1);
        int p1 = atomicAdd(&d_cursor[r.y], 1);
        int p2 = atomicAdd(&d_cursor[r.z], 1);
        int p3 = atomicAdd(&d_cursor[r.w], 1);
        d_edges_sorted[p0] = make_int2(c.x, __float_as_int(v.x));
        d_edges_sorted[p1] = make_int2(c.y, __float_as_int(v.y));
        d_edges_sorted[p2] = make_int2(c.z, __float_as_int(v.z));
        d_edges_sorted[p3] = make_int2(c.w, __float_as_int(v.w));
    } else {
        for (; e < n_edges; ++e) {
            int p = atomicAdd(&d_cursor[edge_row[e]], 1);
            d_edges_sorted[p] = make_int2(edge_col[e], __float_as_int(edge_val[e]));
        }
    }
}

// ---------------------------------------------------------------------------
// embs[:,0,:] = concat(user_emb, item_emb)
// ---------------------------------------------------------------------------
__global__ void lgcn_init_kernel(const float* __restrict__ user_emb,
                                 const float* __restrict__ item_emb,
                                 float* __restrict__ embs,
                                 int n_users, int n) {
    int idx = blockIdx.x * blockDim.x + threadIdx.x;
    int total = n * (D / 4);
    if (idx >= total) return;
    int node = idx >> 4;
    int q    = idx & 15;
    const float4* src = (node < n_users)
        ? reinterpret_cast<const float4*>(user_emb + (size_t)node * D)
        : reinterpret_cast<const float4*>(item_emb + (size_t)(node - n_users) * D);
    reinterpret_cast<float4*>(embs + (size_t)node * NODE_STRIDE)[q] = src[q];
}

// ---------------------------------------------------------------------------
// SpMM, CSR, warp-per-row, float2 lanes, manual unroll-4.
// Edge meta streamed (__ldcs); x rows cached (__ldg).
// Layer 3 additionally fuses the 4-layer mean and writes users/items.
// ---------------------------------------------------------------------------
__global__ void __launch_bounds__(256)
lgcn_spmm_csr(const float* __restrict__ x_base,   // embs + (l-1)*64
              float*       __restrict__ y_base,   // embs + l*64
              int n,
              float* __restrict__ users,          // only used when do_mean
              float* __restrict__ items,
              int n_users, int do_mean) {
    int warp = (blockIdx.x * blockDim.x + threadIdx.x) >> 5;
    if (warp >= n) return;
    int lane = threadIdx.x & 31;

    int e   = d_row_ptr[warp];
    int end = d_row_ptr[warp + 1];

    float ax0 = 0.f, ay0 = 0.f, ax1 = 0.f, ay1 = 0.f;
    float ax2 = 0.f, ay2 = 0.f, ax3 = 0.f, ay3 = 0.f;

    for (; e + 3 < end; e += 4) {
        int2 m0 = __ldcs(&d_edges_sorted[e]);
        int2 m1 = __ldcs(&d_edges_sorted[e + 1]);
        int2 m2 = __ldcs(&d_edges_sorted[e + 2]);
        int2 m3 = __ldcs(&d_edges_sorted[e + 3]);
        float w0 = __int_as_float(m0.y), w1 = __int_as_float(m1.y);
        float w2 = __int_as_float(m2.y), w3 = __int_as_float(m3.y);
        float2 v0 = __ldg(&reinterpret_cast<const float2*>(x_base + (size_t)m0.x * NODE_STRIDE)[lane]);
        float2 v1 = __ldg(&reinterpret_cast<const float2*>(x_base + (size_t)m1.x * NODE_STRIDE)[lane]);
        float2 v2 = __ldg(&reinterpret_cast<const float2*>(x_base + (size_t)m2.x * NODE_STRIDE)[lane]);
        float2 v3 = __ldg(&reinterpret_cast<const float2*>(x_base + (size_t)m3.x * NODE_STRIDE)[lane]);
        ax0 += w0 * v0.x;  ay0 += w0 * v0.y;
        ax1 += w1 * v1.x;  ay1 += w1 * v1.y;
        ax2 += w2 * v2.x;  ay2 += w2 * v2.y;
        ax3 += w3 * v3.x;  ay3 += w3 * v3.y;
    }
    for (; e < end; ++e) {
        int2 m0 = __ldcs(&d_edges_sorted[e]);
        float w0 = __int_as_float(m0.y);
        float2 v0 = __ldg(&reinterpret_cast<const float2*>(x_base + (size_t)m0.x * NODE_STRIDE)[lane]);
        ax0 += w0 * v0.x;  ay0 += w0 * v0.y;
    }

    float rx = (ax0 + ax1) + (ax2 + ax3);
    float ry = (ay0 + ay1) + (ay2 + ay3);

    reinterpret_cast<float2*>(y_base + (size_t)warp * NODE_STRIDE)[lane] =
        make_float2(rx, ry);

    if (do_mean) {
        // y_base == embs + 3*D here; node block base = y_base - 3*D
        const float* nb = y_base - 3 * D + (size_t)warp * NODE_STRIDE;
        float2 l0 = reinterpret_cast<const float2*>(nb)[lane];
        float2 l1 = reinterpret_cast<const float2*>(nb + D)[lane];
        float2 l2 = reinterpret_cast<const float2*>(nb + 2 * D)[lane];
        float mx = (l0.x + l1.x + l2.x + rx) * 0.25f;
        float my = (l0.y + l1.y + l2.y + ry) * 0.25f;
        float* dst = (warp < n_users)
            ? users + (size_t)warp * D
            : items + (size_t)(warp - n_users) * D;
        reinterpret_cast<float2*>(dst)[lane] = make_float2(mx, my);
    }
}

// ---------------------------------------------------------------------------
// out layout = [users (n_users*64)] [items (n_items*64)] [embs (n*4*64)]
// ---------------------------------------------------------------------------
extern "C" void kernel_launch(void* const* d_in, const int* in_sizes, int n_in,
                              void* d_out, int out_size) {
    const float* user_emb = (const float*)d_in[0];
    const float* item_emb = (const float*)d_in[1];
    const int*   edge_row = (const int*)d_in[2];
    const int*   edge_col = (const int*)d_in[3];
    const float* edge_val = (const float*)d_in[4];

    int n_users = in_sizes[0] / D;
    int n_items = in_sizes[1] / D;
    int n       = n_users + n_items;
    int n_edges = in_sizes[2];

    float* out   = (float*)d_out;
    float* users = out;
    float* items = out + (size_t)n_users * D;
    float* embs  = out + (size_t)n * D;   // [n][4][64]

    const int TPB = 256;
    int nb = (n + SCAN_BS - 1) / SCAN_BS;

    // --- CSR build ---
    {
        void* cnt_ptr = nullptr;
        cudaGetSymbolAddress(&cnt_ptr, d_cnt);
        cudaMemsetAsync(cnt_ptr, 0, (size_t)n * sizeof(int), 0);
    }
    {
        int nt = (n_edges + 3) / 4;
        lgcn_hist4<<<(nt + TPB - 1) / TPB, TPB>>>(edge_row, n_edges);
    }
    lgcn_scan_blocks<<<nb, SCAN_BS>>>(n);
    lgcn_scan_sums<<<1, SCAN_BS>>>(nb);
    lgcn_scan_add<<<(n + TPB - 1) / TPB, TPB>>>(n, n_edges);
    {
        int nt = (n_edges + 3) / 4;
        lgcn_scatter4<<<(nt + TPB - 1) / TPB, TPB>>>(edge_row, edge_col, edge_val, n_edges);
    }

    // --- layer 0 init ---
    {
        int total = n * (D / 4);
        lgcn_init_kernel<<<(total + TPB - 1) / TPB, TPB>>>(user_emb, item_emb, embs,
                                                           n_users, n);
    }

    // --- 3 SpMM layers; layer 3 fuses the mean ---
    {
        long long threads = (long long)n * 32;
        int grid = (int)((threads + TPB - 1) / TPB);
        for (int l = 1; l <= 3; ++l) {
            lgcn_spmm_csr<<<grid, TPB>>>(embs + (size_t)(l - 1) * D,
                                         embs + (size_t)l * D,
                                         n, users, items, n_users,
                                         (l == 3) ? 1 : 0);
        }
    }
}

// round 5
// speedup vs baseline: 1.1375x; 1.1375x over previous
#include <cuda_runtime.h>
#include <cstdint>

#define D 64
#define NODE_STRIDE 256        // 4 layers * 64 floats, node-major [n][4][64]
#define MAX_NODES   150016
#define MAX_EDGES   3000000
#define SCAN_BS     512

// ---------------------------------------------------------------------------
// Static scratch (allocation-free rule: __device__ globals)
// ---------------------------------------------------------------------------
__device__ int  d_cnt[MAX_NODES];
__device__ int  d_row_ptr[MAX_NODES + 1];
__device__ int  d_cursor[MAX_NODES];
__device__ int  d_bsums[SCAN_BS];
__device__ int2 d_edges_sorted[MAX_EDGES];   // (col, val bits), grouped by row

// ---------------------------------------------------------------------------
// CSR build (round-2 scalar versions — verified fastest so far)
// ---------------------------------------------------------------------------
__global__ void lgcn_hist(const int* __restrict__ edge_row, int n_edges) {
    int e = blockIdx.x * blockDim.x + threadIdx.x;
    if (e < n_edges) atomicAdd(&d_cnt[edge_row[e]], 1);
}

__global__ void lgcn_scan_blocks(int n) {
    __shared__ int s[SCAN_BS];
    int t = threadIdx.x;
    int i = blockIdx.x * SCAN_BS + t;
    int v = (i < n) ? d_cnt[i] : 0;
    s[t] = v;
    __syncthreads();
    #pragma unroll
    for (int off = 1; off < SCAN_BS; off <<= 1) {
        int tmp = (t >= off) ? s[t - off] : 0;
        __syncthreads();
        s[t] += tmp;
        __syncthreads();
    }
    if (i < n) d_row_ptr[i] = s[t] - v;      // exclusive
    if (t == SCAN_BS - 1) d_bsums[blockIdx.x] = s[t];
}

__global__ void lgcn_scan_sums(int nb) {
    __shared__ int s[SCAN_BS];
    int t = threadIdx.x;
    int v = (t < nb) ? d_bsums[t] : 0;
    s[t] = v;
    __syncthreads();
    #pragma unroll
    for (int off = 1; off < SCAN_BS; off <<= 1) {
        int tmp = (t >= off) ? s[t - off] : 0;
        __syncthreads();
        s[t] += tmp;
        __syncthreads();
    }
    if (t < nb) d_bsums[t] = s[t] - v;       // exclusive
}

__global__ void lgcn_scan_add(int n, int n_edges) {
    int i = blockIdx.x * blockDim.x + threadIdx.x;
    if (i < n) {
        int p = d_row_ptr[i] + d_bsums[i / SCAN_BS];
        d_row_ptr[i] = p;
        d_cursor[i]  = p;
    }
    if (i == 0) d_row_ptr[n] = n_edges;
}

__global__ void lgcn_scatter(const int*   __restrict__ edge_row,
                             const int*   __restrict__ edge_col,
                             const float* __restrict__ edge_val,
                             int n_edges) {
    int e = blockIdx.x * blockDim.x + threadIdx.x;
    if (e >= n_edges) return;
    int r = edge_row[e];
    int p = atomicAdd(&d_cursor[r], 1);
    d_edges_sorted[p] = make_int2(edge_col[e], __float_as_int(edge_val[e]));
}

// ---------------------------------------------------------------------------
// embs[:,0,:] = concat(user_emb, item_emb)
// ---------------------------------------------------------------------------
__global__ void lgcn_init_kernel(const float* __restrict__ user_emb,
                                 const float* __restrict__ item_emb,
                                 float* __restrict__ embs,
                                 int n_users, int n) {
    int idx = blockIdx.x * blockDim.x + threadIdx.x;
    int total = n * (D / 4);
    if (idx >= total) return;
    int node = idx >> 4;
    int q    = idx & 15;
    const float4* src = (node < n_users)
        ? reinterpret_cast<const float4*>(user_emb + (size_t)node * D)
        : reinterpret_cast<const float4*>(item_emb + (size_t)(node - n_users) * D);
    reinterpret_cast<float4*>(embs + (size_t)node * NODE_STRIDE)[q] = src[q];
}

// ---------------------------------------------------------------------------
// SpMM, CSR, warp-per-row, no atomics. EXACT round-2 inner loop
// (plain loads, float2 lanes, unroll-2). Optional fused 4-layer mean tail.
// ---------------------------------------------------------------------------
__global__ void lgcn_spmm_csr(const float* __restrict__ x_base,  // embs + (l-1)*64
                              float*       __restrict__ y_base,  // embs + l*64
                              int n,
                              float* __restrict__ users,
                              float* __restrict__ items,
                              int n_users, int do_mean) {
    int warp = (blockIdx.x * blockDim.x + threadIdx.x) >> 5;
    int lane = threadIdx.x & 31;
    if (warp >= n) return;

    int start = d_row_ptr[warp];
    int end   = d_row_ptr[warp + 1];

    float ax = 0.f, ay = 0.f, bx = 0.f, by = 0.f;

    int e = start;
    for (; e + 1 < end; e += 2) {
        int2 m0 = d_edges_sorted[e];
        int2 m1 = d_edges_sorted[e + 1];
        float w0 = __int_as_float(m0.y);
        float w1 = __int_as_float(m1.y);
        float2 v0 = reinterpret_cast<const float2*>(x_base + (size_t)m0.x * NODE_STRIDE)[lane];
        float2 v1 = reinterpret_cast<const float2*>(x_base + (size_t)m1.x * NODE_STRIDE)[lane];
        ax += w0 * v0.x;  ay += w0 * v0.y;
        bx += w1 * v1.x;  by += w1 * v1.y;
    }
    if (e < end) {
        int2 m0 = d_edges_sorted[e];
        float w0 = __int_as_float(m0.y);
        float2 v0 = reinterpret_cast<const float2*>(x_base + (size_t)m0.x * NODE_STRIDE)[lane];
        ax += w0 * v0.x;  ay += w0 * v0.y;
    }

    float rx = ax + bx;
    float ry = ay + by;

    reinterpret_cast<float2*>(y_base + (size_t)warp * NODE_STRIDE)[lane] =
        make_float2(rx, ry);

    if (do_mean) {
        // y_base == embs + 3*D here; node block base = y_base - 3*D
        const float* nb = y_base - 3 * D + (size_t)warp * NODE_STRIDE;
        float2 l0 = reinterpret_cast<const float2*>(nb)[lane];
        float2 l1 = reinterpret_cast<const float2*>(nb + D)[lane];
        float2 l2 = reinterpret_cast<const float2*>(nb + 2 * D)[lane];
        float mx = (l0.x + l1.x + l2.x + rx) * 0.25f;
        float my = (l0.y + l1.y + l2.y + ry) * 0.25f;
        float* dst = (warp < n_users)
            ? users + (size_t)warp * D
            : items + (size_t)(warp - n_users) * D;
        reinterpret_cast<float2*>(dst)[lane] = make_float2(mx, my);
    }
}

// ---------------------------------------------------------------------------
// out layout = [users (n_users*64)] [items (n_items*64)] [embs (n*4*64)]
// ---------------------------------------------------------------------------
extern "C" void kernel_launch(void* const* d_in, const int* in_sizes, int n_in,
                              void* d_out, int out_size) {
    const float* user_emb = (const float*)d_in[0];
    const float* item_emb = (const float*)d_in[1];
    const int*   edge_row = (const int*)d_in[2];
    const int*   edge_col = (const int*)d_in[3];
    const float* edge_val = (const float*)d_in[4];

    int n_users = in_sizes[0] / D;
    int n_items = in_sizes[1] / D;
    int n       = n_users + n_items;
    int n_edges = in_sizes[2];

    float* out   = (float*)d_out;
    float* users = out;
    float* items = out + (size_t)n_users * D;
    float* embs  = out + (size_t)n * D;   // [n][4][64]

    const int TPB = 256;
    int nb = (n + SCAN_BS - 1) / SCAN_BS;

    // --- CSR build ---
    {
        void* cnt_ptr = nullptr;
        cudaGetSymbolAddress(&cnt_ptr, d_cnt);
        cudaMemsetAsync(cnt_ptr, 0, (size_t)n * sizeof(int), 0);
    }
    lgcn_hist<<<(n_edges + TPB - 1) / TPB, TPB>>>(edge_row, n_edges);
    lgcn_scan_blocks<<<nb, SCAN_BS>>>(n);
    lgcn_scan_sums<<<1, SCAN_BS>>>(nb);
    lgcn_scan_add<<<(n + TPB - 1) / TPB, TPB>>>(n, n_edges);
    lgcn_scatter<<<(n_edges + TPB - 1) / TPB, TPB>>>(edge_row, edge_col, edge_val, n_edges);

    // --- layer 0 init ---
    {
        int total = n * (D / 4);
        lgcn_init_kernel<<<(total + TPB - 1) / TPB, TPB>>>(user_emb, item_emb, embs,
                                                           n_users, n);
    }

    // --- 3 SpMM layers (CSR gather-reduce); layer 3 fuses the mean ---
    {
        long long threads = (long long)n * 32;
        int grid = (int)((threads + TPB - 1) / TPB);
        for (int l = 1; l <= 3; ++l) {
            lgcn_spmm_csr<<<grid, TPB>>>(embs + (size_t)(l - 1) * D,
                                         embs + (size_t)l * D,
                                         n, users, items, n_users,
                                         (l == 3) ? 1 : 0);
        }
    }
}

// round 6
// speedup vs baseline: 1.3562x; 1.1923x over previous
#include <cuda_runtime.h>
#include <cuda_fp16.h>
#include <cstdint>

#define D 64
#define NODE_STRIDE 256        // 4 layers * 64 floats, node-major [n][4][64]
#define MAX_NODES   150016
#define MAX_EDGES   3000000
#define SCAN_BS     512

// ---------------------------------------------------------------------------
// Static scratch (allocation-free rule: __device__ globals)
// ---------------------------------------------------------------------------
__device__ int     d_cnt[MAX_NODES];
__device__ int     d_row_ptr[MAX_NODES + 1];
__device__ int     d_cursor[MAX_NODES];
__device__ int     d_bsums[SCAN_BS];
__device__ int2    d_edges_sorted[MAX_EDGES];        // (col, val bits), grouped by row
__device__ __half2 d_shadow[2][MAX_NODES * 32];      // fp16 ping-pong embeddings, 128B/row

// ---------------------------------------------------------------------------
// CSR build (round-2 scalar versions — verified fastest)
// ---------------------------------------------------------------------------
__global__ void lgcn_hist(const int* __restrict__ edge_row, int n_edges) {
    int e = blockIdx.x * blockDim.x + threadIdx.x;
    if (e < n_edges) atomicAdd(&d_cnt[edge_row[e]], 1);
}

__global__ void lgcn_scan_blocks(int n) {
    __shared__ int s[SCAN_BS];
    int t = threadIdx.x;
    int i = blockIdx.x * SCAN_BS + t;
    int v = (i < n) ? d_cnt[i] : 0;
    s[t] = v;
    __syncthreads();
    #pragma unroll
    for (int off = 1; off < SCAN_BS; off <<= 1) {
        int tmp = (t >= off) ? s[t - off] : 0;
        __syncthreads();
        s[t] += tmp;
        __syncthreads();
    }
    if (i < n) d_row_ptr[i] = s[t] - v;      // exclusive
    if (t == SCAN_BS - 1) d_bsums[blockIdx.x] = s[t];
}

__global__ void lgcn_scan_sums(int nb) {
    __shared__ int s[SCAN_BS];
    int t = threadIdx.x;
    int v = (t < nb) ? d_bsums[t] : 0;
    s[t] = v;
    __syncthreads();
    #pragma unroll
    for (int off = 1; off < SCAN_BS; off <<= 1) {
        int tmp = (t >= off) ? s[t - off] : 0;
        __syncthreads();
        s[t] += tmp;
        __syncthreads();
    }
    if (t < nb) d_bsums[t] = s[t] - v;       // exclusive
}

__global__ void lgcn_scan_add(int n, int n_edges) {
    int i = blockIdx.x * blockDim.x + threadIdx.x;
    if (i < n) {
        int p = d_row_ptr[i] + d_bsums[i / SCAN_BS];
        d_row_ptr[i] = p;
        d_cursor[i]  = p;
    }
    if (i == 0) d_row_ptr[n] = n_edges;
}

__global__ void lgcn_scatter(const int*   __restrict__ edge_row,
                             const int*   __restrict__ edge_col,
                             const float* __restrict__ edge_val,
                             int n_edges) {
    int e = blockIdx.x * blockDim.x + threadIdx.x;
    if (e >= n_edges) return;
    int r = edge_row[e];
    int p = atomicAdd(&d_cursor[r], 1);
    d_edges_sorted[p] = make_int2(edge_col[e], __float_as_int(edge_val[e]));
}

// ---------------------------------------------------------------------------
// embs[:,0,:] = concat(user_emb, item_emb); also write fp16 shadow[0]
// ---------------------------------------------------------------------------
__global__ void lgcn_init_kernel(const float* __restrict__ user_emb,
                                 const float* __restrict__ item_emb,
                                 float* __restrict__ embs,
                                 int n_users, int n) {
    int idx = blockIdx.x * blockDim.x + threadIdx.x;
    int total = n * (D / 4);
    if (idx >= total) return;
    int node = idx >> 4;
    int q    = idx & 15;
    const float4* src = (node < n_users)
        ? reinterpret_cast<const float4*>(user_emb + (size_t)node * D)
        : reinterpret_cast<const float4*>(item_emb + (size_t)(node - n_users) * D);
    float4 v = src[q];
    reinterpret_cast<float4*>(embs + (size_t)node * NODE_STRIDE)[q] = v;

    __half2 h0 = __float22half2_rn(make_float2(v.x, v.y));
    __half2 h1 = __float22half2_rn(make_float2(v.z, v.w));
    d_shadow[0][(size_t)node * 32 + q * 2]     = h0;
    d_shadow[0][(size_t)node * 32 + q * 2 + 1] = h1;
}

// ---------------------------------------------------------------------------
// SpMM, CSR, warp-per-row. Gathers from fp16 shadow (128B/row), accumulates
// fp32, writes fp32 layer + fp16 shadow for the next layer.
// Round-2 loop structure (plain loads, unroll-2). Layer 3 fuses the mean.
// ---------------------------------------------------------------------------
__global__ void lgcn_spmm_csr(const __half2* __restrict__ xh,      // shadow in
                              __half2*       __restrict__ xh_out,  // shadow out (may be null)
                              float*         __restrict__ y_base,  // embs + l*64
                              int n,
                              float* __restrict__ users,
                              float* __restrict__ items,
                              int n_users, int do_mean) {
    int warp = (blockIdx.x * blockDim.x + threadIdx.x) >> 5;
    int lane = threadIdx.x & 31;
    if (warp >= n) return;

    int start = d_row_ptr[warp];
    int end   = d_row_ptr[warp + 1];

    float ax = 0.f, ay = 0.f, bx = 0.f, by = 0.f;

    int e = start;
    for (; e + 1 < end; e += 2) {
        int2 m0 = d_edges_sorted[e];
        int2 m1 = d_edges_sorted[e + 1];
        float w0 = __int_as_float(m0.y);
        float w1 = __int_as_float(m1.y);
        float2 v0 = __half22float2(xh[(size_t)m0.x * 32 + lane]);
        float2 v1 = __half22float2(xh[(size_t)m1.x * 32 + lane]);
        ax += w0 * v0.x;  ay += w0 * v0.y;
        bx += w1 * v1.x;  by += w1 * v1.y;
    }
    if (e < end) {
        int2 m0 = d_edges_sorted[e];
        float w0 = __int_as_float(m0.y);
        float2 v0 = __half22float2(xh[(size_t)m0.x * 32 + lane]);
        ax += w0 * v0.x;  ay += w0 * v0.y;
    }

    float rx = ax + bx;
    float ry = ay + by;

    reinterpret_cast<float2*>(y_base + (size_t)warp * NODE_STRIDE)[lane] =
        make_float2(rx, ry);

    if (xh_out)
        xh_out[(size_t)warp * 32 + lane] = __float22half2_rn(make_float2(rx, ry));

    if (do_mean) {
        // y_base == embs + 3*D here; node block base = y_base - 3*D
        const float* nb = y_base - 3 * D + (size_t)warp * NODE_STRIDE;
        float2 l0 = reinterpret_cast<const float2*>(nb)[lane];
        float2 l1 = reinterpret_cast<const float2*>(nb + D)[lane];
        float2 l2 = reinterpret_cast<const float2*>(nb + 2 * D)[lane];
        float mx = (l0.x + l1.x + l2.x + rx) * 0.25f;
        float my = (l0.y + l1.y + l2.y + ry) * 0.25f;
        float* dst = (warp < n_users)
            ? users + (size_t)warp * D
            : items + (size_t)(warp - n_users) * D;
        reinterpret_cast<float2*>(dst)[lane] = make_float2(mx, my);
    }
}

// ---------------------------------------------------------------------------
// out layout = [users (n_users*64)] [items (n_items*64)] [embs (n*4*64)]
// ---------------------------------------------------------------------------
extern "C" void kernel_launch(void* const* d_in, const int* in_sizes, int n_in,
                              void* d_out, int out_size) {
    const float* user_emb = (const float*)d_in[0];
    const float* item_emb = (const float*)d_in[1];
    const int*   edge_row = (const int*)d_in[2];
    const int*   edge_col = (const int*)d_in[3];
    const float* edge_val = (const float*)d_in[4];

    int n_users = in_sizes[0] / D;
    int n_items = in_sizes[1] / D;
    int n       = n_users + n_items;
    int n_edges = in_sizes[2];

    float* out   = (float*)d_out;
    float* users = out;
    float* items = out + (size_t)n_users * D;
    float* embs  = out + (size_t)n * D;   // [n][4][64]

    const int TPB = 256;
    int nb = (n + SCAN_BS - 1) / SCAN_BS;

    // --- CSR build ---
    {
        void* cnt_ptr = nullptr;
        cudaGetSymbolAddress(&cnt_ptr, d_cnt);
        cudaMemsetAsync(cnt_ptr, 0, (size_t)n * sizeof(int), 0);
    }
    lgcn_hist<<<(n_edges + TPB - 1) / TPB, TPB>>>(edge_row, n_edges);
    lgcn_scan_blocks<<<nb, SCAN_BS>>>(n);
    lgcn_scan_sums<<<1, SCAN_BS>>>(nb);
    lgcn_scan_add<<<(n + TPB - 1) / TPB, TPB>>>(n, n_edges);
    lgcn_scatter<<<(n_edges + TPB - 1) / TPB, TPB>>>(edge_row, edge_col, edge_val, n_edges);

    // --- layer 0 init (fp32 + fp16 shadow) ---
    {
        int total = n * (D / 4);
        lgcn_init_kernel<<<(total + TPB - 1) / TPB, TPB>>>(user_emb, item_emb, embs,
                                                           n_users, n);
    }

    // --- 3 SpMM layers; fp16 shadow ping-pong; layer 3 fuses the mean ---
    {
        __half2* sh0 = nullptr;
        __half2* sh1 = nullptr;
        cudaGetSymbolAddress((void**)&sh0, d_shadow);
        sh1 = sh0 + (size_t)MAX_NODES * 32;

        long long threads = (long long)n * 32;
        int grid = (int)((threads + TPB - 1) / TPB);

        // layer 1: read shadow0, write shadow1
        lgcn_spmm_csr<<<grid, TPB>>>(sh0, sh1, embs + 1 * D, n,
                                     users, items, n_users, 0);
        // layer 2: read shadow1, write shadow0
        lgcn_spmm_csr<<<grid, TPB>>>(sh1, sh0, embs + 2 * D, n,
                                     users, items, n_users, 0);
        // layer 3: read shadow0, no shadow write, fused mean
        lgcn_spmm_csr<<<grid, TPB>>>(sh0, nullptr, embs + 3 * D, n,
                                     users, items, n_users, 1);
    }
}